// round 7
// baseline (speedup 1.0000x reference)
#include <cuda_runtime.h>
#include <cuda_fp16.h>
#include <cstdint>

// ---------------------------------------------------------------------------
// Problem dims (fixed by the dataset)
// ---------------------------------------------------------------------------
#define HDIM 4096
#define IDIM 14336
#define MDIM 4096   // BT * S = 2 * 2048
#define RNK  16

__constant__ float c_nf4[16] = {
  -1.0f, -0.6961928009986877f, -0.5250730514526367f, -0.39491748809814453f,
  -0.28444138169288635f, -0.18477343022823334f, -0.09105003625154495f, 0.0f,
  0.07958029955625534f, 0.16093020141124725f, 0.24611230194568634f,
  0.33791524171829224f, 0.44070982933044434f, 0.5626170039176941f,
  0.7229568362236023f, 1.0f};

// ---------------------------------------------------------------------------
// Scratch (static __device__ arrays: allocation-free per harness rules)
// ---------------------------------------------------------------------------
__device__ __half g_xh  [(size_t)MDIM * HDIM];
__device__ __half g_Wqkv[(size_t)HDIM * HDIM];
__device__ __half g_Wo  [(size_t)HDIM * HDIM];
__device__ __half g_Wgu [(size_t)2 * IDIM * HDIM];
__device__ __half g_Wd  [(size_t)HDIM * IDIM];
__device__ __half g_attn[(size_t)MDIM * HDIM];
__device__ __half g_x1h [(size_t)MDIM * HDIM];
__device__ float  g_x1f [(size_t)MDIM * HDIM];
__device__ __half g_gu  [(size_t)MDIM * 2 * IDIM];
__device__ __half g_hb  [(size_t)MDIM * IDIM];

// ---------------------------------------------------------------------------
// Dequant + LoRA-fold:  W[o,h] = mul * ( sum_j NF4[codes_j[o,h]]*scales_j[o,h/64]
//                                        + sum_r B[o,r]*A[r,h] )
// NSUM = 3 fuses q,k,v into one weight (mul = 1/3, rank 48 stacked adapter).
// ---------------------------------------------------------------------------
template<int NSUM>
__global__ void dq_kernel(const int* __restrict__ codes,
                          const float* __restrict__ scales,
                          const float* __restrict__ Amat,   // [16*NSUM, K] (planes contiguous)
                          const float* __restrict__ Bmat,   // [O, 16] per plane, plane stride bPlane
                          __half* __restrict__ W,
                          int O, int K,
                          long codePlane, long scalePlane, long bPlane,
                          float mul)
{
  constexpr int RR = 16 * NSUM;
  constexpr int HT = 256;
  constexpr int OT = 32;
  extern __shared__ float sA[];        // [RR][HT]
  __shared__ float sB[OT * 48];        // [OT][RR]
  const int tid = threadIdx.x;         // 256 threads
  const int h0 = blockIdx.x * HT;
  const int o0 = blockIdx.y * OT;

  for (int i = tid; i < RR * HT; i += 256) {
    int r = i / HT, c = i - r * HT;
    sA[i] = Amat[(long)r * K + h0 + c];
  }
  for (int i = tid; i < OT * RR; i += 256) {
    int oi = i / RR, r = i - oi * RR;
    sB[oi * RR + r] = Bmat[(long)(r >> 4) * bPlane + (long)(o0 + oi) * RNK + (r & 15)];
  }
  __syncthreads();

  const int h  = h0 + tid;
  const int hb = h >> 6;
  for (int oi = 0; oi < OT; ++oi) {
    const int o = o0 + oi;
    float acc = 0.f;
    #pragma unroll
    for (int j = 0; j < NSUM; ++j) {
      int   c = codes [(long)j * codePlane  + (long)o * K         + h];
      float s = scales[(long)j * scalePlane + (long)o * (K >> 6)  + hb];
      acc += c_nf4[c & 15] * s;
    }
    float lacc = 0.f;
    #pragma unroll
    for (int r = 0; r < RR; ++r) lacc += sB[oi * RR + r] * sA[r * HT + tid];
    W[(long)o * K + h] = __float2half((acc + lacc) * mul);
  }
}

// ---------------------------------------------------------------------------
// fp16 GEMM:  C[M,N] = A[M,K] @ B[N,K]^T  (both K-contiguous), fp32 accum.
// Tile 128x128x64, 8 warps (2x4), warp tile 64x32, mma.sync.m16n8k16,
// 3-stage cp.async pipeline, SW-style xor swizzle on 128B rows.
// EPI: 0 -> store half(C);  1 -> f = resid + C, store f32 + half;  2 -> f32 only.
// ---------------------------------------------------------------------------
#define BM 128
#define BN 128
#define BK 64
#define STG 3
#define SMEM_GEMM (STG * (BM + BN) * BK * 2)

__device__ __forceinline__ void cp16(uint32_t dst, const void* src) {
  asm volatile("cp.async.cg.shared.global [%0], [%1], 16;" :: "r"(dst), "l"(src));
}

__device__ __forceinline__ void gemm_load_stage(const __half* __restrict__ Ag,
                                                const __half* __restrict__ Bg,
                                                long Kdim, int m0, int n0,
                                                int lrow, int lcc,
                                                uint32_t sbase, int st, int kt)
{
  const long k0 = (long)kt * BK;
  uint32_t sA = sbase + (uint32_t)st * (BM + BN) * BK * 2u;
  uint32_t sB = sA + BM * BK * 2u;
  const __half* gA = Ag + (long)(m0 + lrow) * Kdim + k0 + lcc * 8;
  const __half* gB = Bg + (long)(n0 + lrow) * Kdim + k0 + lcc * 8;
  #pragma unroll
  for (int i = 0; i < 4; ++i) {
    int row = lrow + i * 32;
    uint32_t off = (uint32_t)row * 128u + ((uint32_t)(lcc ^ (row & 7)) << 4);
    cp16(sA + off, gA + (long)i * 32 * Kdim);
    cp16(sB + off, gB + (long)i * 32 * Kdim);
  }
  asm volatile("cp.async.commit_group;");
}

template<int EPI>
__global__ void __launch_bounds__(256, 1)
gemm_kernel(const __half* __restrict__ Ag, const __half* __restrict__ Bg,
            const float* __restrict__ Rg, __half* __restrict__ OH,
            float* __restrict__ OF, int Ndim, int Kdim)
{
  extern __shared__ __half smem[];
  const int tid  = threadIdx.x;
  const int m0   = blockIdx.x * BM;   // m fastest -> W n-band reused across wave (L2)
  const int n0   = blockIdx.y * BN;
  const uint32_t sbase = (uint32_t)__cvta_generic_to_shared(smem);
  const int warp = tid >> 5, lane = tid & 31;
  const int wm = warp & 1, wn = warp >> 1;
  const int lrow = tid >> 3, lcc = tid & 7;
  const int KT = Kdim / BK;

  float acc[4][4][4];
  #pragma unroll
  for (int a = 0; a < 4; ++a)
    #pragma unroll
    for (int b = 0; b < 4; ++b)
      #pragma unroll
      for (int c = 0; c < 4; ++c) acc[a][b][c] = 0.f;

  gemm_load_stage(Ag, Bg, Kdim, m0, n0, lrow, lcc, sbase, 0, 0);
  gemm_load_stage(Ag, Bg, Kdim, m0, n0, lrow, lcc, sbase, 1, 1);

  for (int kt = 0; kt < KT; ++kt) {
    if (kt + 1 < KT) asm volatile("cp.async.wait_group 1;");
    else             asm volatile("cp.async.wait_group 0;");
    __syncthreads();
    if (kt + 2 < KT)
      gemm_load_stage(Ag, Bg, Kdim, m0, n0, lrow, lcc, sbase, (kt + 2) % STG, kt + 2);

    uint32_t sA = sbase + (uint32_t)(kt % STG) * (BM + BN) * BK * 2u;
    uint32_t sB = sA + BM * BK * 2u;
    #pragma unroll
    for (int ks = 0; ks < 4; ++ks) {
      const int kk = ks * 16;
      uint32_t af[4][4];
      #pragma unroll
      for (int mi = 0; mi < 4; ++mi) {
        int row = wm * 64 + mi * 16 + (lane & 15);
        int col = kk + (lane >> 4) * 8;
        uint32_t addr = sA + (uint32_t)row * 128u +
                        ((uint32_t)(((col >> 3) ^ (row & 7))) << 4);
        asm volatile("ldmatrix.sync.aligned.m8n8.x4.shared.b16 {%0,%1,%2,%3}, [%4];"
                     : "=r"(af[mi][0]), "=r"(af[mi][1]), "=r"(af[mi][2]), "=r"(af[mi][3])
                     : "r"(addr));
      }
      uint32_t bf[4][2];
      #pragma unroll
      for (int nb = 0; nb < 2; ++nb) {
        int row = wn * 32 + nb * 16 + (lane & 7) + ((lane >> 4) << 3);
        int col = kk + ((lane >> 3) & 1) * 8;
        uint32_t addr = sB + (uint32_t)row * 128u +
                        ((uint32_t)(((col >> 3) ^ (row & 7))) << 4);
        asm volatile("ldmatrix.sync.aligned.m8n8.x4.shared.b16 {%0,%1,%2,%3}, [%4];"
                     : "=r"(bf[2*nb][0]), "=r"(bf[2*nb][1]),
                       "=r"(bf[2*nb+1][0]), "=r"(bf[2*nb+1][1])
                     : "r"(addr));
      }
      #pragma unroll
      for (int mi = 0; mi < 4; ++mi)
        #pragma unroll
        for (int ni = 0; ni < 4; ++ni)
          asm volatile("mma.sync.aligned.m16n8k16.row.col.f32.f16.f16.f32 "
                       "{%0,%1,%2,%3}, {%4,%5,%6,%7}, {%8,%9}, {%0,%1,%2,%3};"
                       : "+f"(acc[mi][ni][0]), "+f"(acc[mi][ni][1]),
                         "+f"(acc[mi][ni][2]), "+f"(acc[mi][ni][3])
                       : "r"(af[mi][0]), "r"(af[mi][1]), "r"(af[mi][2]), "r"(af[mi][3]),
                         "r"(bf[ni][0]), "r"(bf[ni][1]));
    }
  }

  // Epilogue (registers only, no sync needed)
  const long mbase = m0 + wm * 64 + (lane >> 2);
  const long nbase = n0 + wn * 32 + (lane & 3) * 2;
  #pragma unroll
  for (int mi = 0; mi < 4; ++mi) {
    #pragma unroll
    for (int ni = 0; ni < 4; ++ni) {
      long r = mbase + mi * 16;
      long c = nbase + ni * 8;
      long i0 = r * Ndim + c;
      long i1 = (r + 8) * Ndim + c;
      float v0 = acc[mi][ni][0], v1 = acc[mi][ni][1];
      float v2 = acc[mi][ni][2], v3 = acc[mi][ni][3];
      if (EPI >= 1) {
        float2 ra = *(const float2*)(Rg + i0);
        float2 rb = *(const float2*)(Rg + i1);
        v0 += ra.x; v1 += ra.y; v2 += rb.x; v3 += rb.y;
        *(float2*)(OF + i0) = make_float2(v0, v1);
        *(float2*)(OF + i1) = make_float2(v2, v3);
      }
      if (EPI <= 1) {
        *(__half2*)(OH + i0) = __floats2half2_rn(v0, v1);
        *(__half2*)(OH + i1) = __floats2half2_rn(v2, v3);
      }
    }
  }
}

// ---------------------------------------------------------------------------
// Elementwise kernels
// ---------------------------------------------------------------------------
__global__ void cvt_kernel(const float* __restrict__ x, __half* __restrict__ y) {
  long i = ((long)blockIdx.x * 256 + threadIdx.x) * 2;
  float2 v = *(const float2*)(x + i);
  *(__half2*)(y + i) = __floats2half2_rn(v.x, v.y);
}

__global__ void silu_kernel(const __half* __restrict__ gu, __half* __restrict__ ho) {
  const long m = blockIdx.y;
  const long c = ((long)blockIdx.x * 256 + threadIdx.x) * 2;
  const long base = m * (2L * IDIM);
  __half2 g2 = *(const __half2*)(gu + base + c);
  __half2 u2 = *(const __half2*)(gu + base + IDIM + c);
  float g0 = __half2float(__low2half(g2)), g1 = __half2float(__high2half(g2));
  float u0 = __half2float(__low2half(u2)), u1 = __half2float(__high2half(u2));
  float h0 = g0 / (1.f + __expf(-g0)) * u0;
  float h1 = g1 / (1.f + __expf(-g1)) * u1;
  *(__half2*)(ho + m * (long)IDIM + c) = __floats2half2_rn(h0, h1);
}

// ---------------------------------------------------------------------------
// Host driver (graph-capturable: kernel launches only)
// ---------------------------------------------------------------------------
extern "C" void kernel_launch(void* const* d_in, const int* in_sizes, int n_in,
                              void* d_out, int out_size) {
  const float* x           = (const float*)d_in[0];
  const int*   codes_attn  = (const int*)  d_in[1];
  const float* scales_attn = (const float*)d_in[2];
  const int*   codes_gu    = (const int*)  d_in[3];
  const float* scales_gu   = (const float*)d_in[4];
  const int*   codes_down  = (const int*)  d_in[5];
  const float* scales_down = (const float*)d_in[6];
  const float* lora_A_h    = (const float*)d_in[7];
  const float* lora_A_down = (const float*)d_in[8];
  const float* lora_B_attn = (const float*)d_in[9];
  const float* lora_B_gu   = (const float*)d_in[10];
  const float* lora_B_down = (const float*)d_in[11];
  (void)in_sizes; (void)n_in; (void)out_size;

  __half *xh, *Wqkv, *Wo, *Wgu, *Wd, *attn, *x1h, *gu, *hb;
  float *x1f;
  cudaGetSymbolAddress((void**)&xh,   g_xh);
  cudaGetSymbolAddress((void**)&Wqkv, g_Wqkv);
  cudaGetSymbolAddress((void**)&Wo,   g_Wo);
  cudaGetSymbolAddress((void**)&Wgu,  g_Wgu);
  cudaGetSymbolAddress((void**)&Wd,   g_Wd);
  cudaGetSymbolAddress((void**)&attn, g_attn);
  cudaGetSymbolAddress((void**)&x1h,  g_x1h);
  cudaGetSymbolAddress((void**)&x1f,  g_x1f);
  cudaGetSymbolAddress((void**)&gu,   g_gu);
  cudaGetSymbolAddress((void**)&hb,   g_hb);

  cudaFuncSetAttribute(gemm_kernel<0>, cudaFuncAttributeMaxDynamicSharedMemorySize, SMEM_GEMM);
  cudaFuncSetAttribute(gemm_kernel<1>, cudaFuncAttributeMaxDynamicSharedMemorySize, SMEM_GEMM);
  cudaFuncSetAttribute(gemm_kernel<2>, cudaFuncAttributeMaxDynamicSharedMemorySize, SMEM_GEMM);
  cudaFuncSetAttribute(dq_kernel<3>,   cudaFuncAttributeMaxDynamicSharedMemorySize, 48 * 256 * 4);

  // x -> fp16
  cvt_kernel<<<(MDIM * (long)HDIM) / 512, 256>>>(x, xh);

  // Dequant + LoRA fold (qkv fused with mul = 1/3)
  dim3 dqg_attn(HDIM / 256, HDIM / 32);
  dq_kernel<3><<<dqg_attn, 256, 48 * 256 * 4>>>(
      codes_attn, scales_attn, lora_A_h, lora_B_attn, Wqkv, HDIM, HDIM,
      (long)HDIM * HDIM, (long)HDIM * (HDIM / 64), (long)HDIM * RNK, 1.f / 3.f);
  dq_kernel<1><<<dqg_attn, 256, 16 * 256 * 4>>>(
      codes_attn + 3L * HDIM * HDIM, scales_attn + 3L * HDIM * (HDIM / 64),
      lora_A_h + 3L * RNK * HDIM, lora_B_attn + 3L * HDIM * RNK,
      Wo, HDIM, HDIM, 0, 0, 0, 1.f);
  dim3 dqg_gu(HDIM / 256, IDIM / 32);
  dq_kernel<1><<<dqg_gu, 256, 16 * 256 * 4>>>(
      codes_gu, scales_gu, lora_A_h + 4L * RNK * HDIM, lora_B_gu,
      Wgu, IDIM, HDIM, 0, 0, 0, 1.f);
  dq_kernel<1><<<dqg_gu, 256, 16 * 256 * 4>>>(
      codes_gu + (long)IDIM * HDIM, scales_gu + (long)IDIM * (HDIM / 64),
      lora_A_h + 5L * RNK * HDIM, lora_B_gu + (long)IDIM * RNK,
      Wgu + (long)IDIM * HDIM, IDIM, HDIM, 0, 0, 0, 1.f);
  dim3 dqg_d(IDIM / 256, HDIM / 32);
  dq_kernel<1><<<dqg_d, 256, 16 * 256 * 4>>>(
      codes_down, scales_down, lora_A_down, lora_B_down,
      Wd, HDIM, IDIM, 0, 0, 0, 1.f);

  // attn = xh @ Wqkv^T    (already = (q+k+v)/3)
  gemm_kernel<0><<<dim3(MDIM / 128, HDIM / 128), 256, SMEM_GEMM>>>(
      xh, Wqkv, nullptr, attn, nullptr, HDIM, HDIM);
  // x1 = x + attn @ Wo^T  (store fp32 + fp16)
  gemm_kernel<1><<<dim3(MDIM / 128, HDIM / 128), 256, SMEM_GEMM>>>(
      attn, Wo, x, x1h, x1f, HDIM, HDIM);
  // [g | u] = x1h @ Wgu^T
  gemm_kernel<0><<<dim3(MDIM / 128, (2 * IDIM) / 128), 256, SMEM_GEMM>>>(
      x1h, Wgu, nullptr, gu, nullptr, 2 * IDIM, HDIM);
  // h = silu(g) * u
  silu_kernel<<<dim3(IDIM / 512, MDIM), 256>>>(gu, hb);
  // out = x1 + h @ Wd^T   (fp32 to d_out)
  gemm_kernel<2><<<dim3(MDIM / 128, HDIM / 128), 256, SMEM_GEMM>>>(
      hb, Wd, x1f, nullptr, (float*)d_out, HDIM, IDIM);
}